// round 15
// baseline (speedup 1.0000x reference)
#include <cuda_runtime.h>
#include <math.h>

#define FULLMASK 0xffffffffu

// Composed register-bit CNOT relabel (wires 5..9 = reg bits 0..4), per layer:
#define RSRC(r) ( ((r)&1) \
    | (((((r)>>1)^(r))&1)<<1) \
    | (((((r)>>2)^((r)>>1)^(r))&1)<<2) \
    | (((((r)>>3)^((r)>>2))&1)<<3) \
    | (((((r)>>4)^((r)>>3)^((r)>>2))&1)<<4) )

// Frame-tracked lane-wire constants (A_k = (Mrev^-1)^k, verified round 4):
__device__ __constant__ const int MK[6][5] = {
    { 3,14,12,24,16},
    {13,26,20, 8,16},
    {23, 6,28,24,16},
    {17, 2, 4, 8,16},
    {19,14,12,24,16},
    {29,26,20, 8,16}
};
__device__ __constant__ const int SK[6][5] = {
    {1,3,7,12,28},
    {1,2,5,11,23},
    {1,3,6,14,25},
    {1,2,4,8,17},
    {1,3,7,12,29},
    {1,2,5,11,22}
};
__device__ __constant__ const int CK[6] = {16,28,23,25,17,29};
__device__ __constant__ const int MROW[5] = {1,2,5,11,22};

// Cross-kernel scratch (device globals; no allocation)
__device__ float gUV[8192 * 20];   // per-sample u[10] then v[10]
__device__ float gTan[60];         // tan(qw/2)
__device__ float gCt;              // prod of all 60 cos(qw/2)

__device__ __forceinline__ float fast_tanh(float x) {
    float e;
    asm("ex2.approx.f32 %0, %1;" : "=f"(e) : "f"(x * 2.88539008177792681f));
    return (e - 1.0f) * __frcp_rn(e + 1.0f);
}

// dual-fp32 FMA / MUL on the f32x2 pipe (float2<->double reinterpret = reg-pair no-op)
__device__ __forceinline__ float2 ffma2(float2 a, float2 b, float2 c) {
    double da = *reinterpret_cast<double*>(&a);
    double db = *reinterpret_cast<double*>(&b);
    double dc = *reinterpret_cast<double*>(&c);
    double dd;
    asm("fma.rn.f32x2 %0, %1, %2, %3;" : "=d"(dd) : "d"(da), "d"(db), "d"(dc));
    return *reinterpret_cast<float2*>(&dd);
}
__device__ __forceinline__ float2 fmul2(float2 a, float2 b) {
    double da = *reinterpret_cast<double*>(&a);
    double db = *reinterpret_cast<double*>(&b);
    double dd;
    asm("mul.rn.f32x2 %0, %1, %2;" : "=d"(dd) : "d"(da), "d"(db));
    return *reinterpret_cast<float2*>(&dd);
}

// half accessor for packed state: logical reg index r -> st[r>>1].x/.y
#define GETH(st, r) (((r) & 1) ? (st)[(r) >> 1].y : (st)[(r) >> 1].x)

// ---------------------------------------------------------------------------
// Kernel 1: dense layer -> per-sample u/v; also tan table + cosine product.
// Runs its heavy LDG/LDS traffic WITHOUT competing with the shuffle kernel.
// ---------------------------------------------------------------------------
__global__ __launch_bounds__(256)
void angles_kernel(const float* __restrict__ x,
                   const float* __restrict__ W1,
                   const float* __restrict__ b1,
                   const float* __restrict__ qw)
{
    __shared__ alignas(16) float sW1[10][512];
    __shared__ float scc[64];

    const int tid = threadIdx.x;

#pragma unroll 4
    for (int i = tid; i < 5120; i += 256) {
        int d = i / 10, q = i - d * 10;
        sW1[q][d] = W1[i];
    }
    if (blockIdx.x == 0 && tid < 60) {
        float th = 0.5f * qw[tid];
        float s = __sinf(th), c = __cosf(th);
        gTan[tid] = s * __frcp_rn(c);
        scc[tid] = c;
    }
    __syncthreads();
    if (blockIdx.x == 0 && tid == 0) {
        float p = 1.f;
#pragma unroll
        for (int i = 0; i < 60; i++) p *= scc[i];
        gCt = p;
    }

    const int warp = tid >> 5;
    const int lane = tid & 31;
    const int sample = blockIdx.x * 8 + warp;
    const float* xr = x + (size_t)sample * 512;

    const float4* x4 = (const float4*)xr;
    float4 xv[4];
#pragma unroll
    for (int t = 0; t < 4; t++) xv[t] = __ldg(&x4[lane + 32 * t]);

#pragma unroll
    for (int q = 0; q < 10; q++) {
        const float4* w4 = (const float4*)(&sW1[q][0]);
        float2 acc = make_float2(0.f, 0.f);
#pragma unroll
        for (int t = 0; t < 4; t++) {
            float4 wv = w4[lane + 32 * t];
            acc = ffma2(make_float2(xv[t].x, xv[t].y), make_float2(wv.x, wv.y), acc);
            acc = ffma2(make_float2(xv[t].z, xv[t].w), make_float2(wv.z, wv.w), acc);
        }
        float p = acc.x + acc.y;
#pragma unroll
        for (int off = 16; off; off >>= 1) p += __shfl_xor_sync(FULLMASK, p, off);
        float ang = fast_tanh(p + __ldg(&b1[q])) * 1.57079632679489662f;
        float hh = 0.5f * ang;
        float sn = __sinf(hh), cs = __cosf(hh);
        float uq = (cs - sn) * 0.70710678118654752f;
        float vq = (cs + sn) * 0.70710678118654752f;
        if (lane == 0) {
            gUV[sample * 20 + q]      = uq;
            gUV[sample * 20 + 10 + q] = vq;
        }
    }
}

// ---------------------------------------------------------------------------
// Kernel 2: pure statevector circuit — shfl + FFMA2, no smem, no syncthreads.
// ---------------------------------------------------------------------------
__global__ __launch_bounds__(128, 10)
void dq_kernel(const float* __restrict__ W2,
               const float* __restrict__ b2,
               float* __restrict__ out)
{
    const int tid = threadIdx.x;
    const int warp = tid >> 5;
    const int lane = tid & 31;
    const int sample = blockIdx.x * 4 + warp;

    // ---- per-sample u/v (uniform broadcast loads, L1-hit) ----
    float u[10], v[10];
    const float* uvp = gUV + sample * 20;
#pragma unroll
    for (int q = 0; q < 10; q++) {
        u[q] = __ldg(&uvp[q]);
        v[q] = __ldg(&uvp[10 + q]);
    }

    // ---- build product state (packed pairs), prescaled by cosine product ----
    float2 st[16];
    {
        float L = __ldg(&gCt);
#pragma unroll
        for (int w = 0; w < 5; w++) L *= ((lane >> w) & 1) ? v[w] : u[w];
        st[0].x = L * u[5];
        st[0].y = L * v[5];
#pragma unroll
        for (int b = 0; b < 4; b++) {
            const int m = 1 << b;
            const int w = 6 + b;
            float2 uu = make_float2(u[w], u[w]);
            float2 vv = make_float2(v[w], v[w]);
#pragma unroll
            for (int j = 0; j < 16; j++) {
                if (j < m) {
                    st[j + m] = fmul2(st[j], vv);
                    st[j]     = fmul2(st[j], uu);
                }
            }
        }
    }

    // ---- 6 layers (frame-tracked; cosines prescaled) ----
#pragma unroll
    for (int k = 0; k < 6; k++) {
        // (1) mixed CNOT(4,5): conditional within-pair swap
        {
            const bool qsw = (__popc(lane & CK[k]) & 1);
#pragma unroll
            for (int j = 0; j < 16; j++) {
                float a = st[j].x, b = st[j].y;
                st[j].x = qsw ? b : a;
                st[j].y = qsw ? a : b;
            }
        }
        // (2) reg CNOTs: compile-time half-gather relabel
        {
            float2 tp[16];
#pragma unroll
            for (int j = 0; j < 16; j++) {
                tp[j].x = GETH(st, RSRC(2 * j));
                tp[j].y = GETH(st, RSRC(2 * j + 1));
            }
#pragma unroll
            for (int j = 0; j < 16; j++) st[j] = tp[j];
        }
        // (3) lane-RYs: 2 SHFL + 1 FFMA2 per packed pair (fp32 transport)
#pragma unroll
        for (int w = 0; w < 5; w++) {
            const int m = MK[k][w];
            const float t = __ldg(&gTan[k * 10 + w]);
            float tq = (__popc(lane & SK[k][w]) & 1) ? t : -t;
            float2 t2 = make_float2(tq, tq);
#pragma unroll
            for (int j = 0; j < 16; j++) {
                float2 o;
                o.x = __shfl_xor_sync(FULLMASK, st[j].x, m);
                o.y = __shfl_xor_sync(FULLMASK, st[j].y, m);
                st[j] = ffma2(t2, o, st[j]);
            }
        }
        // (4a) reg-RY wire 5 (within-pair, scalar)
        {
            float tw = __ldg(&gTan[k * 10 + 5]);
#pragma unroll
            for (int j = 0; j < 16; j++) {
                float a0 = st[j].x, a1 = st[j].y;
                st[j].x = fmaf(-tw, a1, a0);
                st[j].y = fmaf( tw, a0, a1);
            }
        }
        // (4b) reg-RY wires 6-9 (cross-pair, FFMA2)
#pragma unroll
        for (int b = 0; b < 4; b++) {
            float tw = __ldg(&gTan[k * 10 + 6 + b]);
            float2 nt2 = make_float2(-tw, -tw);
            float2 pt2 = make_float2( tw,  tw);
            const int M = 1 << b;
#pragma unroll
            for (int j = 0; j < 16; j++) {
                if ((j & M) == 0) {
                    float2 A = st[j], B = st[j + M];
                    st[j]     = ffma2(nt2, B, A);
                    st[j + M] = ffma2(pt2, A, B);
                }
            }
        }
    }

    // ---- measurement ----
#pragma unroll
    for (int j = 0; j < 16; j++) st[j] = fmul2(st[j], st[j]);

    float e[10];
    float T;
    // reg wires 5..9: pair-tree over packed halves, then lane all-reduce
    {
        float p0[16], p1[8], p2[4], p3[2];
        float d0 = 0.f, d1 = 0.f, d2 = 0.f, d3 = 0.f, d4;
#pragma unroll
        for (int i = 0; i < 16; i++) { p0[i] = st[i].x + st[i].y; d0 += st[i].x - st[i].y; }
#pragma unroll
        for (int i = 0; i < 8; i++)  { p1[i] = p0[2*i] + p0[2*i+1]; d1 += p0[2*i] - p0[2*i+1]; }
#pragma unroll
        for (int i = 0; i < 4; i++)  { p2[i] = p1[2*i] + p1[2*i+1]; d2 += p1[2*i] - p1[2*i+1]; }
#pragma unroll
        for (int i = 0; i < 2; i++)  { p3[i] = p2[2*i] + p2[2*i+1]; d3 += p2[2*i] - p2[2*i+1]; }
        d4 = p3[0] - p3[1];
        T  = p3[0] + p3[1];
        float dd[5] = {d0, d1, d2, d3, d4};
#pragma unroll
        for (int b = 0; b < 5; b++) {
            float acc = dd[b];
#pragma unroll
            for (int off = 16; off; off >>= 1) acc += __shfl_xor_sync(FULLMASK, acc, off);
            e[5 + b] = acc;
        }
    }
    // lane wires: signed WHT (5 shfl) + 5 broadcasts at rows of A6
    {
        float xwh = T;
#pragma unroll
        for (int j = 0; j < 5; j++) {
            float o = __shfl_xor_sync(FULLMASK, xwh, 1 << j);
            xwh = ((lane >> j) & 1) ? (o - xwh) : (xwh + o);
        }
#pragma unroll
        for (int w = 0; w < 5; w++)
            e[w] = __shfl_sync(FULLMASK, xwh, MROW[w]);
    }

    // ---- out = e @ W2 + b2 (coalesced global reads; L1-resident) ----
#pragma unroll
    for (int t = 0; t < 2; t++) {
        int o = lane + 32 * t;
        float acc = __ldg(&b2[o]);
#pragma unroll
        for (int q = 0; q < 10; q++) acc = fmaf(e[q], __ldg(&W2[q * 64 + o]), acc);
        out[(size_t)sample * 64 + o] = acc;
    }
}

extern "C" void kernel_launch(void* const* d_in, const int* in_sizes, int n_in,
                              void* d_out, int out_size) {
    const float* x  = (const float*)d_in[0];
    const float* W1 = (const float*)d_in[1];
    const float* b1 = (const float*)d_in[2];
    const float* qw = (const float*)d_in[3];
    const float* W2 = (const float*)d_in[4];
    const float* b2 = (const float*)d_in[5];
    float* out = (float*)d_out;

    int B = in_sizes[0] / 512;          // 8192

    // Stage 1: dense layer -> u/v per sample (heavy LDG isolated here)
    angles_kernel<<<B / 8, 256>>>(x, W1, b1, qw);
    // Stage 2: pure shuffle/FFMA2 statevector circuit
    dq_kernel<<<B / 4, 128>>>(W2, b2, out);
}

// round 16
// speedup vs baseline: 1.0198x; 1.0198x over previous
#include <cuda_runtime.h>
#include <math.h>

#define FULLMASK 0xffffffffu

// Composed register-bit CNOT relabel (wires 5..9 = reg bits 0..4), per layer:
#define RSRC(r) ( ((r)&1) \
    | (((((r)>>1)^(r))&1)<<1) \
    | (((((r)>>2)^((r)>>1)^(r))&1)<<2) \
    | (((((r)>>3)^((r)>>2))&1)<<3) \
    | (((((r)>>4)^((r)>>3)^((r)>>2))&1)<<4) )

// Frame-tracked lane-wire constants (A_k = (Mrev^-1)^k, verified round 4):
__device__ __constant__ const int MK[6][5] = {
    { 3,14,12,24,16},
    {13,26,20, 8,16},
    {23, 6,28,24,16},
    {17, 2, 4, 8,16},
    {19,14,12,24,16},
    {29,26,20, 8,16}
};
__device__ __constant__ const int SK[6][5] = {
    {1,3,7,12,28},
    {1,2,5,11,23},
    {1,3,6,14,25},
    {1,2,4,8,17},
    {1,3,7,12,29},
    {1,2,5,11,22}
};
__device__ __constant__ const int CK[6] = {16,28,23,25,17,29};
__device__ __constant__ const int MROW[5] = {1,2,5,11,22};

// Cross-kernel scratch (device globals; no allocation)
__device__ float gW1T[10 * 512];   // transposed W1 [q][d]
__device__ float gUV[8192 * 20];   // per-sample u[10] then v[10]
__device__ float gTan[60];         // tan(qw/2)
__device__ float gCt;              // prod of all 60 cos(qw/2)

__device__ __forceinline__ float fast_tanh(float x) {
    float e;
    asm("ex2.approx.f32 %0, %1;" : "=f"(e) : "f"(x * 2.88539008177792681f));
    return (e - 1.0f) * __frcp_rn(e + 1.0f);
}

// dual-fp32 FMA / MUL on the f32x2 pipe (float2<->double reinterpret = reg-pair no-op)
__device__ __forceinline__ float2 ffma2(float2 a, float2 b, float2 c) {
    double da = *reinterpret_cast<double*>(&a);
    double db = *reinterpret_cast<double*>(&b);
    double dc = *reinterpret_cast<double*>(&c);
    double dd;
    asm("fma.rn.f32x2 %0, %1, %2, %3;" : "=d"(dd) : "d"(da), "d"(db), "d"(dc));
    return *reinterpret_cast<float2*>(&dd);
}
__device__ __forceinline__ float2 fmul2(float2 a, float2 b) {
    double da = *reinterpret_cast<double*>(&a);
    double db = *reinterpret_cast<double*>(&b);
    double dd;
    asm("mul.rn.f32x2 %0, %1, %2;" : "=d"(dd) : "d"(da), "d"(db));
    return *reinterpret_cast<float2*>(&dd);
}

// half accessor for packed state: logical reg index r -> st[r>>1].x/.y
#define GETH(st, r) (((r) & 1) ? (st)[(r) >> 1].y : (st)[(r) >> 1].x)

// ---------------------------------------------------------------------------
// Kernel 0: transpose W1 + tan/cos tables (tiny)
// ---------------------------------------------------------------------------
__global__ __launch_bounds__(256)
void prep_kernel(const float* __restrict__ W1, const float* __restrict__ qw) {
    int i = blockIdx.x * 256 + threadIdx.x;
    if (i < 5120) {
        int d = i / 10, q = i - d * 10;
        gW1T[q * 512 + d] = W1[i];
    }
    if (i < 60) {
        float th = 0.5f * qw[i];
        float s = __sinf(th), c = __cosf(th);
        gTan[i] = s * __frcp_rn(c);
    }
    if (i == 0) {
        float p = 1.f;
        for (int j = 0; j < 60; j++) {
            float th = 0.5f * qw[j];
            p *= __cosf(th);
        }
        gCt = p;
    }
}

// ---------------------------------------------------------------------------
// Kernel 1: dense layer -> per-sample u/v. No smem, no syncthreads; W1T via
// __ldg (L1-resident 20KB per SM). Streams x at DRAM rate.
// ---------------------------------------------------------------------------
__global__ __launch_bounds__(256)
void angles_kernel(const float* __restrict__ x,
                   const float* __restrict__ b1)
{
    const int tid = threadIdx.x;
    const int warp = tid >> 5;
    const int lane = tid & 31;
    const int sample = blockIdx.x * 8 + warp;
    const float* xr = x + (size_t)sample * 512;

    const float4* x4 = (const float4*)xr;
    float4 xv[4];
#pragma unroll
    for (int t = 0; t < 4; t++) xv[t] = __ldg(&x4[lane + 32 * t]);

#pragma unroll
    for (int q = 0; q < 10; q++) {
        const float4* w4 = (const float4*)(gW1T + q * 512);
        float2 acc = make_float2(0.f, 0.f);
#pragma unroll
        for (int t = 0; t < 4; t++) {
            float4 wv = __ldg(&w4[lane + 32 * t]);
            acc = ffma2(make_float2(xv[t].x, xv[t].y), make_float2(wv.x, wv.y), acc);
            acc = ffma2(make_float2(xv[t].z, xv[t].w), make_float2(wv.z, wv.w), acc);
        }
        float p = acc.x + acc.y;
#pragma unroll
        for (int off = 16; off; off >>= 1) p += __shfl_xor_sync(FULLMASK, p, off);
        float ang = fast_tanh(p + __ldg(&b1[q])) * 1.57079632679489662f;
        float hh = 0.5f * ang;
        float sn = __sinf(hh), cs = __cosf(hh);
        float uq = (cs - sn) * 0.70710678118654752f;
        float vq = (cs + sn) * 0.70710678118654752f;
        if (lane == 0) {
            gUV[sample * 20 + q]      = uq;
            gUV[sample * 20 + 10 + q] = vq;
        }
    }
}

// ---------------------------------------------------------------------------
// Kernel 2: pure statevector circuit — shfl + FFMA2, no smem, no syncthreads.
// ---------------------------------------------------------------------------
__global__ __launch_bounds__(128, 10)
void dq_kernel(const float* __restrict__ W2,
               const float* __restrict__ b2,
               float* __restrict__ out)
{
    const int tid = threadIdx.x;
    const int warp = tid >> 5;
    const int lane = tid & 31;
    const int sample = blockIdx.x * 4 + warp;

    // ---- per-sample u/v (uniform broadcast loads, L1-hit) ----
    float u[10], v[10];
    const float* uvp = gUV + sample * 20;
#pragma unroll
    for (int q = 0; q < 10; q++) {
        u[q] = __ldg(&uvp[q]);
        v[q] = __ldg(&uvp[10 + q]);
    }

    // ---- build product state (packed pairs), prescaled by cosine product ----
    float2 st[16];
    {
        float L = __ldg(&gCt);
#pragma unroll
        for (int w = 0; w < 5; w++) L *= ((lane >> w) & 1) ? v[w] : u[w];
        st[0].x = L * u[5];
        st[0].y = L * v[5];
#pragma unroll
        for (int b = 0; b < 4; b++) {
            const int m = 1 << b;
            const int w = 6 + b;
            float2 uu = make_float2(u[w], u[w]);
            float2 vv = make_float2(v[w], v[w]);
#pragma unroll
            for (int j = 0; j < 16; j++) {
                if (j < m) {
                    st[j + m] = fmul2(st[j], vv);
                    st[j]     = fmul2(st[j], uu);
                }
            }
        }
    }

    // ---- 6 layers (frame-tracked; cosines prescaled) ----
#pragma unroll
    for (int k = 0; k < 6; k++) {
        // (1) mixed CNOT(4,5): conditional within-pair swap
        {
            const bool qsw = (__popc(lane & CK[k]) & 1);
#pragma unroll
            for (int j = 0; j < 16; j++) {
                float a = st[j].x, b = st[j].y;
                st[j].x = qsw ? b : a;
                st[j].y = qsw ? a : b;
            }
        }
        // (2) reg CNOTs: compile-time half-gather relabel
        {
            float2 tp[16];
#pragma unroll
            for (int j = 0; j < 16; j++) {
                tp[j].x = GETH(st, RSRC(2 * j));
                tp[j].y = GETH(st, RSRC(2 * j + 1));
            }
#pragma unroll
            for (int j = 0; j < 16; j++) st[j] = tp[j];
        }
        // (3) lane-RYs: 2 SHFL + 1 FFMA2 per packed pair (fp32 transport)
#pragma unroll
        for (int w = 0; w < 5; w++) {
            const int m = MK[k][w];
            const float t = __ldg(&gTan[k * 10 + w]);
            float tq = (__popc(lane & SK[k][w]) & 1) ? t : -t;
            float2 t2 = make_float2(tq, tq);
#pragma unroll
            for (int j = 0; j < 16; j++) {
                float2 o;
                o.x = __shfl_xor_sync(FULLMASK, st[j].x, m);
                o.y = __shfl_xor_sync(FULLMASK, st[j].y, m);
                st[j] = ffma2(t2, o, st[j]);
            }
        }
        // (4a) reg-RY wire 5 (within-pair, scalar)
        {
            float tw = __ldg(&gTan[k * 10 + 5]);
#pragma unroll
            for (int j = 0; j < 16; j++) {
                float a0 = st[j].x, a1 = st[j].y;
                st[j].x = fmaf(-tw, a1, a0);
                st[j].y = fmaf( tw, a0, a1);
            }
        }
        // (4b) reg-RY wires 6-9 (cross-pair, FFMA2)
#pragma unroll
        for (int b = 0; b < 4; b++) {
            float tw = __ldg(&gTan[k * 10 + 6 + b]);
            float2 nt2 = make_float2(-tw, -tw);
            float2 pt2 = make_float2( tw,  tw);
            const int M = 1 << b;
#pragma unroll
            for (int j = 0; j < 16; j++) {
                if ((j & M) == 0) {
                    float2 A = st[j], B = st[j + M];
                    st[j]     = ffma2(nt2, B, A);
                    st[j + M] = ffma2(pt2, A, B);
                }
            }
        }
    }

    // ---- measurement ----
#pragma unroll
    for (int j = 0; j < 16; j++) st[j] = fmul2(st[j], st[j]);

    float e[10];
    float T;
    // reg wires 5..9: pair-tree over packed halves, then lane all-reduce
    {
        float p0[16], p1[8], p2[4], p3[2];
        float d0 = 0.f, d1 = 0.f, d2 = 0.f, d3 = 0.f, d4;
#pragma unroll
        for (int i = 0; i < 16; i++) { p0[i] = st[i].x + st[i].y; d0 += st[i].x - st[i].y; }
#pragma unroll
        for (int i = 0; i < 8; i++)  { p1[i] = p0[2*i] + p0[2*i+1]; d1 += p0[2*i] - p0[2*i+1]; }
#pragma unroll
        for (int i = 0; i < 4; i++)  { p2[i] = p1[2*i] + p1[2*i+1]; d2 += p1[2*i] - p1[2*i+1]; }
#pragma unroll
        for (int i = 0; i < 2; i++)  { p3[i] = p2[2*i] + p2[2*i+1]; d3 += p2[2*i] - p2[2*i+1]; }
        d4 = p3[0] - p3[1];
        T  = p3[0] + p3[1];
        float dd[5] = {d0, d1, d2, d3, d4};
#pragma unroll
        for (int b = 0; b < 5; b++) {
            float acc = dd[b];
#pragma unroll
            for (int off = 16; off; off >>= 1) acc += __shfl_xor_sync(FULLMASK, acc, off);
            e[5 + b] = acc;
        }
    }
    // lane wires: signed WHT (5 shfl) + 5 broadcasts at rows of A6
    {
        float xwh = T;
#pragma unroll
        for (int j = 0; j < 5; j++) {
            float o = __shfl_xor_sync(FULLMASK, xwh, 1 << j);
            xwh = ((lane >> j) & 1) ? (o - xwh) : (xwh + o);
        }
#pragma unroll
        for (int w = 0; w < 5; w++)
            e[w] = __shfl_sync(FULLMASK, xwh, MROW[w]);
    }

    // ---- out = e @ W2 + b2 (coalesced global reads; L1-resident) ----
#pragma unroll
    for (int t = 0; t < 2; t++) {
        int o = lane + 32 * t;
        float acc = __ldg(&b2[o]);
#pragma unroll
        for (int q = 0; q < 10; q++) acc = fmaf(e[q], __ldg(&W2[q * 64 + o]), acc);
        out[(size_t)sample * 64 + o] = acc;
    }
}

extern "C" void kernel_launch(void* const* d_in, const int* in_sizes, int n_in,
                              void* d_out, int out_size) {
    const float* x  = (const float*)d_in[0];
    const float* W1 = (const float*)d_in[1];
    const float* b1 = (const float*)d_in[2];
    const float* qw = (const float*)d_in[3];
    const float* W2 = (const float*)d_in[4];
    const float* b2 = (const float*)d_in[5];
    float* out = (float*)d_out;

    int B = in_sizes[0] / 512;          // 8192

    // Stage 0: transpose W1 + tables
    prep_kernel<<<20, 256>>>(W1, qw);
    // Stage 1: dense layer -> u/v per sample (no smem, no syncs; x at DRAM rate)
    angles_kernel<<<B / 8, 256>>>(x, b1);
    // Stage 2: pure shuffle/FFMA2 statevector circuit
    dq_kernel<<<B / 4, 128>>>(W2, b2, out);
}